// round 4
// baseline (speedup 1.0000x reference)
#include <cuda_runtime.h>
#include <cuda_bf16.h>
#include <math.h>

// Problem constants
#define B_   128
#define C_   2048
#define S_   196      // 14*14
#define T_   20
#define HID_ 1024

// GEMM tile config (simple canonical mappings)
#define BM 128
#define BN 128
#define BK 8
#define SSTR 132      // 128 + 4 pad, keeps float4 alignment

// Scratch (device globals; no allocation allowed).
// NOTE: device globals must ONLY be referenced from device code — passing
// them as kernel arguments from host hands over the host shadow address,
// and on GB300 (ATS) writes there silently land in host memory.
__device__ float g_vi [(size_t)B_ * S_ * HID_];   // tanh(l1(vi))
__device__ float g_ha [(size_t)B_ * S_ * HID_];   // tanh(vi_t + vq_t)
__device__ float g_u  [B_ * HID_];
__device__ float g_vqt[B_ * HID_];

// ---------------------------------------------------------------------------
// u = mean over T of v_q   [B,T,HID] -> [B,HID]
// ---------------------------------------------------------------------------
__global__ void mean_kernel(const float* __restrict__ v_q) {
    int idx = blockIdx.x * 256 + threadIdx.x;          // b*1024 + k
    int b = idx >> 10;
    int k = idx & (HID_ - 1);
    const float* p = v_q + (size_t)b * T_ * HID_ + k;
    float s = 0.f;
#pragma unroll
    for (int t = 0; t < T_; t++) s += p[t * HID_];
    g_u[idx] = s * (1.0f / T_);
}

// ---------------------------------------------------------------------------
// g_vi[b,s,n] = tanh( sum_c v_i[b,c,s] * l1_w[n,c] + l1_b[n] )
// grid: (ceil(S/BM)=2, HID/BN=8, B), 256 threads
// ---------------------------------------------------------------------------
__global__ __launch_bounds__(256) void gemm_l1(const float* __restrict__ v_i,
                                               const float* __restrict__ W,
                                               const float* __restrict__ bias) {
    __shared__ float As[BK][SSTR];
    __shared__ float Bs[BK][SSTR];
    int b  = blockIdx.z;
    int s0 = blockIdx.x * BM;
    int n0 = blockIdx.y * BN;
    const float* Ab = v_i + (size_t)b * C_ * S_;
    int tid = threadIdx.x;
    int tx = tid & 15, ty = tid >> 4;

    float acc[8][8] = {};

    int b_n  = tid >> 1;        // 0..127
    int b_kq = (tid & 1) * 4;   // 0 or 4

    for (int k0 = 0; k0 < C_; k0 += BK) {
        // A tile: 128(s) x 8(c) scalars, flat bijection e = tid + 256*t
#pragma unroll
        for (int t = 0; t < 4; t++) {
            int e  = tid + t * 256;     // 0..1023
            int c  = e >> 7;            // 0..7
            int sl = e & 127;           // 0..127
            int s  = s0 + sl;
            As[c][sl] = (s < S_) ? Ab[(size_t)(k0 + c) * S_ + s] : 0.f;
        }
        // B tile: Bs[k][n] = W[n0+n][k0+k]
        {
            float4 w4 = *(const float4*)&W[(size_t)(n0 + b_n) * C_ + k0 + b_kq];
            Bs[b_kq + 0][b_n] = w4.x;
            Bs[b_kq + 1][b_n] = w4.y;
            Bs[b_kq + 2][b_n] = w4.z;
            Bs[b_kq + 3][b_n] = w4.w;
        }
        __syncthreads();
#pragma unroll
        for (int k = 0; k < BK; k++) {
            float ar[8], br[8];
            *(float4*)&ar[0] = *(const float4*)&As[k][ty * 8];
            *(float4*)&ar[4] = *(const float4*)&As[k][ty * 8 + 4];
            *(float4*)&br[0] = *(const float4*)&Bs[k][tx * 8];
            *(float4*)&br[4] = *(const float4*)&Bs[k][tx * 8 + 4];
#pragma unroll
            for (int i = 0; i < 8; i++)
#pragma unroll
                for (int j = 0; j < 8; j++) acc[i][j] += ar[i] * br[j];
        }
        __syncthreads();
    }
#pragma unroll
    for (int i = 0; i < 8; i++) {
        int s = s0 + ty * 8 + i;
        if (s >= S_) continue;
        float* out = g_vi + ((size_t)(b * S_ + s)) * HID_;
#pragma unroll
        for (int j = 0; j < 8; j++) {
            int n = n0 + tx * 8 + j;
            out[n] = tanhf(acc[i][j] + bias[n]);
        }
    }
}

// ---------------------------------------------------------------------------
// g_vqt[b,k] = b_u[k] + sum_h g_u[b,h] * w_u[k,h]
// grid: (B, HID/256), 256 threads
// ---------------------------------------------------------------------------
__global__ __launch_bounds__(256) void vqt_kernel(const float* __restrict__ w_u,
                                                  const float* __restrict__ b_u) {
    __shared__ float su[HID_];
    int b = blockIdx.x;
    int k = blockIdx.y * 256 + threadIdx.x;
    for (int i = threadIdx.x; i < HID_; i += 256) su[i] = g_u[b * HID_ + i];
    __syncthreads();
    const float4* w4 = (const float4*)(w_u + (size_t)k * HID_);
    float acc = b_u[k];
#pragma unroll 4
    for (int h = 0; h < HID_ / 4; h++) {
        float4 w = w4[h];
        acc += w.x * su[h * 4 + 0] + w.y * su[h * 4 + 1] +
               w.z * su[h * 4 + 2] + w.w * su[h * 4 + 3];
    }
    g_vqt[b * HID_ + k] = acc;
}

// ---------------------------------------------------------------------------
// g_ha[m,n] = tanh( sum_h g_vi[m,h] * w_vi[n,h] + g_vqt[m/S, n] )
// grid: (B*S/BM=196, HID/BN=8), 256 threads
// ---------------------------------------------------------------------------
__global__ __launch_bounds__(256) void gemm_hop(const float* __restrict__ W) {
    __shared__ float As[BK][SSTR];
    __shared__ float Bs[BK][SSTR];
    int m0 = blockIdx.x * BM;
    int n0 = blockIdx.y * BN;
    int tid = threadIdx.x;
    int tx = tid & 15, ty = tid >> 4;

    float acc[8][8] = {};

    int r  = tid >> 1;          // 0..127
    int kq = (tid & 1) * 4;     // 0 or 4

    for (int k0 = 0; k0 < HID_; k0 += BK) {
        {
            float4 a4 = *(const float4*)&g_vi[(size_t)(m0 + r) * HID_ + k0 + kq];
            As[kq + 0][r] = a4.x;
            As[kq + 1][r] = a4.y;
            As[kq + 2][r] = a4.z;
            As[kq + 3][r] = a4.w;
            float4 w4 = *(const float4*)&W[(size_t)(n0 + r) * HID_ + k0 + kq];
            Bs[kq + 0][r] = w4.x;
            Bs[kq + 1][r] = w4.y;
            Bs[kq + 2][r] = w4.z;
            Bs[kq + 3][r] = w4.w;
        }
        __syncthreads();
#pragma unroll
        for (int k = 0; k < BK; k++) {
            float ar[8], br[8];
            *(float4*)&ar[0] = *(const float4*)&As[k][ty * 8];
            *(float4*)&ar[4] = *(const float4*)&As[k][ty * 8 + 4];
            *(float4*)&br[0] = *(const float4*)&Bs[k][tx * 8];
            *(float4*)&br[4] = *(const float4*)&Bs[k][tx * 8 + 4];
#pragma unroll
            for (int i = 0; i < 8; i++)
#pragma unroll
                for (int j = 0; j < 8; j++) acc[i][j] += ar[i] * br[j];
        }
        __syncthreads();
    }
#pragma unroll
    for (int i = 0; i < 8; i++) {
        int m = m0 + ty * 8 + i;
        int b = m / S_;
        const float* vq = g_vqt + b * HID_;
        float* out = g_ha + (size_t)m * HID_;
#pragma unroll
        for (int j = 0; j < 8; j++) {
            int n = n0 + tx * 8 + j;
            out[n] = tanhf(acc[i][j] + vq[n]);
        }
    }
}

// ---------------------------------------------------------------------------
// Two-pass softmax over s + weighted sum:
//   p = softmax_s(g_ha[b,:,k]);  u_new[b,k] = g_u[b,k] + sum_s p[s]*g_vi[b,s,k]
// write_to_global=true  -> update device symbol g_u (hop 0)
// write_to_global=false -> write to uout (harness d_out, hop 1)
// grid: (HID/256, B), 256 threads
// ---------------------------------------------------------------------------
__global__ __launch_bounds__(256) void attend_kernel(float* __restrict__ uout,
                                                     int write_to_global) {
    int b = blockIdx.y;
    int k = blockIdx.x * 256 + threadIdx.x;
    const float* ha = g_ha + (size_t)b * S_ * HID_ + k;
    const float* vi = g_vi + (size_t)b * S_ * HID_ + k;
    float mx = -1e30f;
    for (int s = 0; s < S_; s++) mx = fmaxf(mx, ha[(size_t)s * HID_]);
    float l = 0.f, acc = 0.f;
    for (int s = 0; s < S_; s++) {
        float e = __expf(ha[(size_t)s * HID_] - mx);
        l   += e;
        acc += e * vi[(size_t)s * HID_];
    }
    float r = g_u[b * HID_ + k] + acc / l;
    if (write_to_global) g_u[b * HID_ + k] = r;   // device-side symbol ref: correct address
    else                 uout[b * HID_ + k] = r;
}

// ---------------------------------------------------------------------------
extern "C" void kernel_launch(void* const* d_in, const int* in_sizes, int n_in,
                              void* d_out, int out_size) {
    (void)in_sizes; (void)n_in; (void)out_size;
    const float* v_i   = (const float*)d_in[0];
    const float* v_q   = (const float*)d_in[1];
    const float* l1_w  = (const float*)d_in[2];
    const float* l1_b  = (const float*)d_in[3];
    const float* w_vi0 = (const float*)d_in[4];
    const float* w_u0  = (const float*)d_in[5];
    const float* b_u0  = (const float*)d_in[6];
    const float* w_vi1 = (const float*)d_in[7];
    const float* w_u1  = (const float*)d_in[8];
    const float* b_u1  = (const float*)d_in[9];
    float* out = (float*)d_out;

    // u0 = mean_t(v_q)
    mean_kernel<<<(B_ * HID_) / 256, 256>>>(v_q);

    // vi = tanh(l1(v_i^T))
    dim3 g1((S_ + BM - 1) / BM, HID_ / BN, B_);
    gemm_l1<<<g1, 256>>>(v_i, l1_w, l1_b);

    // hop 0 (updates g_u in place, via device-side symbol)
    vqt_kernel<<<dim3(B_, HID_ / 256), 256>>>(w_u0, b_u0);
    gemm_hop<<<dim3((B_ * S_) / BM, HID_ / BN), 256>>>(w_vi0);
    attend_kernel<<<dim3(HID_ / 256, B_), 256>>>(out, 1);

    // hop 1 (writes final output to d_out)
    vqt_kernel<<<dim3(B_, HID_ / 256), 256>>>(w_u1, b_u1);
    gemm_hop<<<dim3((B_ * S_) / BM, HID_ / BN), 256>>>(w_vi1);
    attend_kernel<<<dim3(HID_ / 256, B_), 256>>>(out, 0);
}

// round 6
// speedup vs baseline: 3.9980x; 3.9980x over previous
#include <cuda_runtime.h>
#include <math.h>
#include <stdint.h>

// Problem constants
#define B_   128
#define C_   2048
#define S_   196
#define T_   20
#define HID_ 1024
#define M_TOT (B_ * S_)        // 25088 = 196 * 128

// Scratch (device globals; NEVER pass these from host — ATS makes the host
// shadow address silently writable).
__device__ float g_viT[(size_t)M_TOT * C_];    // transposed v_i [m][c], tf32-rounded
__device__ float g_vi [(size_t)M_TOT * HID_];  // tanh(l1(vi)), tf32-rounded
__device__ float g_ha [(size_t)M_TOT * HID_];  // tanh(vi_t + vq_t)
__device__ float g_u  [B_ * HID_];
__device__ float g_vqt[B_ * HID_];
__device__ float g_wc [(size_t)HID_ * C_];     // tf32-rounded weight copy (8MB)

// ============================ helpers ======================================
__device__ __forceinline__ uint32_t smem_u32(const void* p) {
    uint32_t a;
    asm("{ .reg .u64 t; cvta.to.shared.u64 t, %1; cvt.u32.u64 %0, t; }"
        : "=r"(a) : "l"(p));
    return a;
}
// fp32 -> tf32 round-to-nearest (kills HMMA truncation bias)
__device__ __forceinline__ float ftf32(float x) {
    uint32_t u;
    asm("cvt.rna.tf32.f32 %0, %1;" : "=r"(u) : "f"(x));
    return __uint_as_float(u);
}

#define CP_ASYNC16(sm, gp) asm volatile("cp.async.cg.shared.global [%0], [%1], 16;" :: "r"(sm), "l"(gp))
#define CP_COMMIT()        asm volatile("cp.async.commit_group;" ::: "memory")
#define CP_WAIT(n)         asm volatile("cp.async.wait_group %0;" :: "n"(n) : "memory")

__device__ __forceinline__ void mma_tf32(float* c, const uint32_t* a, const uint32_t* b) {
    asm volatile(
        "mma.sync.aligned.m16n8k8.row.col.f32.tf32.tf32.f32 "
        "{%0,%1,%2,%3}, {%4,%5,%6,%7}, {%8,%9}, {%0,%1,%2,%3};"
        : "+f"(c[0]), "+f"(c[1]), "+f"(c[2]), "+f"(c[3])
        : "r"(a[0]), "r"(a[1]), "r"(a[2]), "r"(a[3]), "r"(b[0]), "r"(b[1]));
}

// Tile layout in smem: 128 rows x 32 k-floats, XOR swizzle:
// byteoff(row,k) = row*128 + ((k>>2) ^ (row&7))*16 + (k&3)*4
#define TILE_B   16384
#define STAGE_B  (2 * TILE_B)    // A tile + B tile
#define STAGES   3
#define GSMEM    (STAGES * STAGE_B)   // 98304

// ============================ small kernels ================================

// v_i [B][C][S] -> g_viT[(b*S+s)][c], tf32-rounded
__global__ __launch_bounds__(256) void transpose_vi(const float* __restrict__ v_i) {
    __shared__ float t[32][33];
    int b  = blockIdx.z;
    int s0 = blockIdx.x * 32;
    int c0 = blockIdx.y * 32;
    int tx = threadIdx.x & 31, ty = threadIdx.x >> 5;   // 32 x 8
#pragma unroll
    for (int i = 0; i < 4; i++) {
        int c = c0 + ty + i * 8, s = s0 + tx;
        t[ty + i * 8][tx] = (s < S_) ? v_i[((size_t)b * C_ + c) * S_ + s] : 0.f;
    }
    __syncthreads();
#pragma unroll
    for (int i = 0; i < 4; i++) {
        int s = s0 + ty + i * 8, c = c0 + tx;
        if (s < S_) g_viT[((size_t)(b * S_ + s)) * C_ + c] = ftf32(t[tx][ty + i * 8]);
    }
}

// tf32-round a weight matrix into g_wc
__global__ __launch_bounds__(256) void cvt_w(const float* __restrict__ w, int n4) {
    int i = blockIdx.x * 256 + threadIdx.x;
    if (i < n4) {
        float4 v = ((const float4*)w)[i];
        v.x = ftf32(v.x); v.y = ftf32(v.y); v.z = ftf32(v.z); v.w = ftf32(v.w);
        ((float4*)g_wc)[i] = v;
    }
}

// u = mean over T of v_q
__global__ void mean_kernel(const float* __restrict__ v_q) {
    int idx = blockIdx.x * 256 + threadIdx.x;
    int b = idx >> 10, k = idx & (HID_ - 1);
    const float* p = v_q + (size_t)b * T_ * HID_ + k;
    float s = 0.f;
#pragma unroll
    for (int t = 0; t < T_; t++) s += p[t * HID_];
    g_u[idx] = s * (1.0f / T_);
}

// g_vqt[b,k] = b_u[k] + sum_h g_u[b,h]*w_u[k,h]
__global__ __launch_bounds__(256) void vqt_kernel(const float* __restrict__ w_u,
                                                  const float* __restrict__ b_u) {
    __shared__ float su[HID_];
    int b = blockIdx.x;
    int k = blockIdx.y * 256 + threadIdx.x;
    for (int i = threadIdx.x; i < HID_; i += 256) su[i] = g_u[b * HID_ + i];
    __syncthreads();
    const float4* w4 = (const float4*)(w_u + (size_t)k * HID_);
    float acc = b_u[k];
#pragma unroll 4
    for (int h = 0; h < HID_ / 4; h++) {
        float4 w = w4[h];
        acc += w.x * su[h * 4] + w.y * su[h * 4 + 1] + w.z * su[h * 4 + 2] + w.w * su[h * 4 + 3];
    }
    g_vqt[b * HID_ + k] = acc;
}

// ---------------------------------------------------------------------------
// TF32 HMMA GEMM: out[m][n] = tanh( sum_k A[m][k]*g_wc[n][k] + addend )
//   MODE 0: A=g_viT, K=2048, out=g_vi (tf32-rounded), addend=bias[n]
//   MODE 1: A=g_vi,  K=1024, out=g_ha,                addend=g_vqt[m/S][n]
// grid (196, 8), 256 threads (8 warps, 2Mx4N of 64x32 warp tiles)
// ---------------------------------------------------------------------------
template <int MODE, int KDIM>
__global__ __launch_bounds__(256, 2) void gemm_mma(const float* __restrict__ bias) {
    extern __shared__ char smem[];
    uint32_t sb = smem_u32(smem);
    const int NC = KDIM / 32;
    int m0 = blockIdx.x * 128, n0 = blockIdx.y * 128;
    int tid = threadIdx.x;
    int wid = tid >> 5, lane = tid & 31;
    int g = lane >> 2, t = lane & 3;
    int warp_m = wid & 1, warp_n = wid >> 1;
    int mBw = warp_m * 64, nBw = warp_n * 32;
    const float* A = (MODE == 0) ? g_viT : g_vi;
    const float* W = g_wc;

    float acc[4][4][4] = {};

    // cp.async one 128x32 chunk pair (A and B) into stage buffer
    auto cp_chunk = [&](int kc, int stg) {
        uint32_t ab = sb + (uint32_t)stg * STAGE_B;
        uint32_t bb = ab + TILE_B;
        int kb = kc * 32;
#pragma unroll
        for (int i = 0; i < 4; i++) {
            int e = tid + 256 * i;           // 0..1023
            int r = e >> 3;                  // 0..127
            int j = e & 7;                   // float4 slot along k
            uint32_t off = (uint32_t)(r * 128 + ((j ^ (r & 7)) * 16));
            CP_ASYNC16(ab + off, &A[(size_t)(m0 + r) * KDIM + kb + j * 4]);
            CP_ASYNC16(bb + off, &W[(size_t)(n0 + r) * KDIM + kb + j * 4]);
        }
    };

    auto compute = [&](int stg) {
        const char* ab = smem + (size_t)stg * STAGE_B;
        const char* bb = ab + TILE_B;
#pragma unroll
        for (int kk = 0; kk < 4; kk++) {
            uint32_t bf[8];
#pragma unroll
            for (int ni = 0; ni < 4; ni++) {
                int n = nBw + ni * 8 + g;
                int sw = n & 7;
                bf[ni * 2 + 0] = *(const uint32_t*)(bb + n * 128 + (((kk * 2)     ^ sw) * 16) + t * 4);
                bf[ni * 2 + 1] = *(const uint32_t*)(bb + n * 128 + (((kk * 2 + 1) ^ sw) * 16) + t * 4);
            }
#pragma unroll
            for (int mi = 0; mi < 4; mi++) {
                int m = mBw + mi * 16 + g;
                int sw = m & 7;                       // (m+8)&7 == m&7
                uint32_t af[4];
                const char* r0 = ab + m * 128;
                af[0] = *(const uint32_t*)(r0 +        (((kk * 2)     ^ sw) * 16) + t * 4);
                af[1] = *(const uint32_t*)(r0 + 1024 + (((kk * 2)     ^ sw) * 16) + t * 4);
                af[2] = *(const uint32_t*)(r0 +        (((kk * 2 + 1) ^ sw) * 16) + t * 4);
                af[3] = *(const uint32_t*)(r0 + 1024 + (((kk * 2 + 1) ^ sw) * 16) + t * 4);
#pragma unroll
                for (int ni = 0; ni < 4; ni++) mma_tf32(acc[mi][ni], af, bf + ni * 2);
            }
        }
    };

    // prologue: fill pipeline
#pragma unroll
    for (int s = 0; s < STAGES - 1; s++) { cp_chunk(s, s); CP_COMMIT(); }

    for (int kc = 0; kc < NC; kc++) {
        CP_WAIT(STAGES - 2);
        __syncthreads();
        compute(kc % STAGES);
        __syncthreads();
        int nx = kc + STAGES - 1;
        if (nx < NC) { cp_chunk(nx, nx % STAGES); CP_COMMIT(); }
    }

    // epilogue: fused addend + tanh, direct stores
    float* OUT = (MODE == 0) ? g_vi : g_ha;
#pragma unroll
    for (int mi = 0; mi < 4; mi++) {
        int m = m0 + mBw + mi * 16 + g;
#pragma unroll
        for (int ni = 0; ni < 4; ni++) {
            int n = n0 + nBw + ni * 8 + t * 2;
            float a0, a1, a2, a3;
            if (MODE == 0) {
                a0 = bias[n]; a1 = bias[n + 1]; a2 = a0; a3 = a1;
            } else {
                int b0 = m / S_, b1 = (m + 8) / S_;
                a0 = g_vqt[b0 * HID_ + n]; a1 = g_vqt[b0 * HID_ + n + 1];
                a2 = g_vqt[b1 * HID_ + n]; a3 = g_vqt[b1 * HID_ + n + 1];
            }
            float v0 = tanhf(acc[mi][ni][0] + a0);
            float v1 = tanhf(acc[mi][ni][1] + a1);
            float v2 = tanhf(acc[mi][ni][2] + a2);
            float v3 = tanhf(acc[mi][ni][3] + a3);
            if (MODE == 0) { v0 = ftf32(v0); v1 = ftf32(v1); v2 = ftf32(v2); v3 = ftf32(v3); }
            float2 p0 = {v0, v1}, p1 = {v2, v3};
            *(float2*)&OUT[(size_t)m * HID_ + n]       = p0;
            *(float2*)&OUT[(size_t)(m + 8) * HID_ + n] = p1;
        }
    }
}

// ---------------------------------------------------------------------------
// softmax over s + weighted sum; write_to_global ? g_u : uout(d_out)
// ---------------------------------------------------------------------------
__global__ __launch_bounds__(256) void attend_kernel(float* __restrict__ uout,
                                                     int write_to_global) {
    int b = blockIdx.y;
    int k = blockIdx.x * 256 + threadIdx.x;
    const float* ha = g_ha + (size_t)b * S_ * HID_ + k;
    const float* vi = g_vi + (size_t)b * S_ * HID_ + k;
    float mx = -1e30f;
    for (int s = 0; s < S_; s++) mx = fmaxf(mx, ha[(size_t)s * HID_]);
    float l = 0.f, acc = 0.f;
    for (int s = 0; s < S_; s++) {
        float e = __expf(ha[(size_t)s * HID_] - mx);
        l   += e;
        acc += e * vi[(size_t)s * HID_];
    }
    float r = g_u[b * HID_ + k] + acc / l;
    if (write_to_global) g_u[b * HID_ + k] = r;
    else                 uout[b * HID_ + k] = r;
}

// ---------------------------------------------------------------------------
extern "C" void kernel_launch(void* const* d_in, const int* in_sizes, int n_in,
                              void* d_out, int out_size) {
    (void)in_sizes; (void)n_in; (void)out_size;
    const float* v_i   = (const float*)d_in[0];
    const float* v_q   = (const float*)d_in[1];
    const float* l1_w  = (const float*)d_in[2];
    const float* l1_b  = (const float*)d_in[3];
    const float* w_vi0 = (const float*)d_in[4];
    const float* w_u0  = (const float*)d_in[5];
    const float* b_u0  = (const float*)d_in[6];
    const float* w_vi1 = (const float*)d_in[7];
    const float* w_u1  = (const float*)d_in[8];
    const float* b_u1  = (const float*)d_in[9];
    float* out = (float*)d_out;

    cudaFuncSetAttribute(gemm_mma<0, C_>,   cudaFuncAttributeMaxDynamicSharedMemorySize, GSMEM);
    cudaFuncSetAttribute(gemm_mma<1, HID_>, cudaFuncAttributeMaxDynamicSharedMemorySize, GSMEM);

    mean_kernel<<<(B_ * HID_) / 256, 256>>>(v_q);
    transpose_vi<<<dim3(7, C_ / 32, B_), 256>>>(v_i);

    dim3 gg(M_TOT / 128, HID_ / 128);   // (196, 8)

    // l1
    cvt_w<<<(HID_ * C_ / 4 + 255) / 256, 256>>>(l1_w, HID_ * C_ / 4);
    gemm_mma<0, C_><<<gg, 256, GSMEM>>>(l1_b);

    // hop 0
    vqt_kernel<<<dim3(B_, HID_ / 256), 256>>>(w_u0, b_u0);
    cvt_w<<<(HID_ * HID_ / 4 + 255) / 256, 256>>>(w_vi0, HID_ * HID_ / 4);
    gemm_mma<1, HID_><<<gg, 256, GSMEM>>>(nullptr);
    attend_kernel<<<dim3(HID_ / 256, B_), 256>>>(out, 1);

    // hop 1
    vqt_kernel<<<dim3(B_, HID_ / 256), 256>>>(w_u1, b_u1);
    cvt_w<<<(HID_ * HID_ / 4 + 255) / 256, 256>>>(w_vi1, HID_ * HID_ / 4);
    gemm_mma<1, HID_><<<gg, 256, GSMEM>>>(nullptr);
    attend_kernel<<<dim3(HID_ / 256, B_), 256>>>(out, 0);
}